// round 16
// baseline (speedup 1.0000x reference)
#include <cuda_runtime.h>
#include <cuda_fp16.h>
#include <cstdint>
#include <math.h>

#define B_    64
#define L_    1024
#define D_    128
#define M_    128
#define DM_   512
#define NL_   4
#define H_    8
#define DH_   64
#define PRED_ 96

// ================= helpers =================
__device__ __forceinline__ uint32_t smem_to_u32(const void* smem_ptr) {
    uint32_t addr;
    asm("{ .reg .u64 tmp; cvta.to.shared.u64 tmp, %1; cvt.u32.u64 %0, tmp; }"
        : "=r"(addr) : "l"(smem_ptr));
    return addr;
}
__device__ __forceinline__ void ldsm_x4(uint32_t& r0, uint32_t& r1, uint32_t& r2,
                                        uint32_t& r3, uint32_t addr) {
    asm volatile("ldmatrix.sync.aligned.m8n8.x4.shared.b16 {%0,%1,%2,%3}, [%4];"
                 : "=r"(r0), "=r"(r1), "=r"(r2), "=r"(r3) : "r"(addr));
}
__device__ __forceinline__ void mma_f16(float* d, const uint32_t* a, uint32_t b0, uint32_t b1) {
    asm volatile(
        "mma.sync.aligned.m16n8k16.row.col.f32.f16.f16.f32 "
        "{%0,%1,%2,%3}, {%4,%5,%6,%7}, {%8,%9}, {%0,%1,%2,%3};"
        : "+f"(d[0]), "+f"(d[1]), "+f"(d[2]), "+f"(d[3])
        : "r"(a[0]), "r"(a[1]), "r"(a[2]), "r"(a[3]), "r"(b0), "r"(b1));
}
__device__ __forceinline__ void cp_async16(uint32_t saddr, const void* gptr) {
    asm volatile("cp.async.cg.shared.global [%0], [%1], 16;" :: "r"(saddr), "l"(gptr));
}
__device__ __forceinline__ void cp_commit() {
    asm volatile("cp.async.commit_group;" ::: "memory");
}
template<int N> __device__ __forceinline__ void cp_wait() {
    asm volatile("cp.async.wait_group %0;" :: "n"(N) : "memory");
}
// packed fp32x2
typedef unsigned long long u64t;
__device__ __forceinline__ u64t pk2(float a, float b) {
    u64t r; asm("mov.b64 %0, {%1, %2};" : "=l"(r) : "f"(a), "f"(b)); return r;
}
__device__ __forceinline__ void upk2(u64t x, float& a, float& b) {
    asm("mov.b64 {%0, %1}, %2;" : "=f"(a), "=f"(b) : "l"(x));
}
__device__ __forceinline__ u64t fma2(u64t a, u64t b, u64t c) {
    u64t d; asm("fma.rn.f32x2 %0, %1, %2, %3;" : "=l"(d) : "l"(a), "l"(b), "l"(c));
    return d;
}

// ---------------- scratch (device globals; no allocation) ----------------
__device__ float g_xt[(size_t)B_ * D_ * L_];
__device__ float g_s[B_ * 2 * D_];
__device__ float g_h2[B_ * 32];
__device__ float g_lower[(size_t)B_ * D_ * M_];
__device__ float g_t[(size_t)B_ * D_ * DM_];
__device__ float g_qkv[(size_t)B_ * D_ * 3 * DM_];
__device__ float g_y[(size_t)B_ * D_ * DM_];
__device__ float g_hp[(size_t)B_ * D_ * M_];

// fp16 single activation buffers
__device__ __half g_zh[(size_t)B_ * D_ * L_];
__device__ __half g_th[(size_t)B_ * D_ * DM_];
__device__ __half g_ctxh[(size_t)B_ * D_ * DM_];
__device__ __half g_midh[(size_t)B_ * D_ * 2 * DM_];

// fp16 hi/lo weight buffers (packed)
#define OFF_EMB  0
#define OFF_QKV  524288
#define OFF_OUT  3670016
#define OFF_FF1  4718592
#define OFF_FF2  6815744
#define OFF_PROJ 8912896
#define W_TOTAL  8978432
__device__ __half g_whi[W_TOTAL];
__device__ __half g_wlo[W_TOTAL];

// ---------------- all-weights fp32 -> (hi, lo) fp16 conversion (one launch) ----------------
__global__ void cvt_all_kernel(const float* __restrict__ s0, const float* __restrict__ s1,
                               const float* __restrict__ s2, const float* __restrict__ s3,
                               const float* __restrict__ s4, const float* __restrict__ s5) {
    int gid = blockIdx.x * 256 + threadIdx.x;
    if (gid >= 2244608) return;
    const float* src; size_t off; int local;
    if (gid < 131072)       { src = s0; off = OFF_EMB;  local = gid; }
    else if (gid < 917504)  { src = s1; off = OFF_QKV;  local = gid - 131072; }
    else if (gid < 1179648) { src = s2; off = OFF_OUT;  local = gid - 917504; }
    else if (gid < 1703936) { src = s3; off = OFF_FF1;  local = gid - 1179648; }
    else if (gid < 2228224) { src = s4; off = OFF_FF2;  local = gid - 1703936; }
    else                    { src = s5; off = OFF_PROJ; local = gid - 2228224; }
    float4 f = ((const float4*)src)[local];
    __half h0 = __float2half(f.x), h1 = __float2half(f.y);
    __half h2 = __float2half(f.z), h3 = __float2half(f.w);
    __half2* hp = (__half2*)(g_whi + off);
    __half2* lp = (__half2*)(g_wlo + off);
    hp[2 * local] = __half2(h0, h1);
    hp[2 * local + 1] = __half2(h2, h3);
    lp[2 * local] = __half2(__float2half(f.x - __half2float(h0)),
                            __float2half(f.y - __half2float(h1)));
    lp[2 * local + 1] = __half2(__float2half(f.z - __half2float(h2)),
                                __float2half(f.w - __half2float(h3)));
}

// ---------------- transpose x [B,L,D] -> g_xt [B,D,L] ----------------
__global__ void transpose_x_kernel(const float* __restrict__ x) {
    __shared__ float tile[32][33];
    int b = blockIdx.z;
    int l0 = blockIdx.x * 32, d0 = blockIdx.y * 32;
    int lx = threadIdx.x, ly = threadIdx.y;
#pragma unroll
    for (int r = 0; r < 32; r += 8)
        tile[ly + r][lx] = x[((size_t)b * L_ + (l0 + ly + r)) * D_ + (d0 + lx)];
    __syncthreads();
#pragma unroll
    for (int r = 0; r < 32; r += 8)
        g_xt[((size_t)b * D_ + (d0 + ly + r)) * L_ + (l0 + lx)] = tile[lx][ly + r];
}

// ---------------- copula: u64-key hybrid bitonic rank -> erfinv z (fp16) ----------------
__global__ __launch_bounds__(1024) void copula_kernel() {
    __shared__ u64t keys[L_];
    __shared__ float vals[L_];
    __shared__ float sq[L_];

    int blk = blockIdx.x;
    int tid = threadIdx.x;

    uint32_t fb = __float_as_uint(g_xt[(size_t)blk * L_ + tid]);
    uint32_t mk = fb ^ ((fb & 0x80000000u) ? 0xFFFFFFFFu : 0x80000000u);
    u64t key = ((u64t)mk << 32) | (uint32_t)tid;

#pragma unroll
    for (int k = 2; k <= 32; k <<= 1) {
#pragma unroll
        for (int j = k >> 1; j > 0; j >>= 1) {
            u64t ko = __shfl_xor_sync(0xffffffffu, key, j);
            bool keepmin = (((tid & k) == 0) == ((tid & j) == 0));
            u64t mn = key < ko ? key : ko;
            u64t mx = key < ko ? ko : key;
            key = keepmin ? mn : mx;
        }
    }
    for (int k = 64; k <= 1024; k <<= 1) {
        keys[tid] = key;
        __syncthreads();
        for (int j = k >> 1; j >= 32; j >>= 1) {
            int ixj = tid ^ j;
            if (ixj > tid) {
                u64t a = keys[tid], b = keys[ixj];
                if ((a > b) == ((tid & k) == 0)) { keys[tid] = b; keys[ixj] = a; }
            }
            __syncthreads();
        }
        key = keys[tid];
#pragma unroll
        for (int j = 16; j > 0; j >>= 1) {
            u64t ko = __shfl_xor_sync(0xffffffffu, key, j);
            bool keepmin = (((tid & k) == 0) == ((tid & j) == 0));
            u64t mn = key < ko ? key : ko;
            u64t mx = key < ko ? ko : key;
            key = keepmin ? mn : mx;
        }
    }
    __syncthreads();
    ((int*)vals)[(uint32_t)(key & 0xFFFFFFFFu)] = tid;
    __syncthreads();
    int r = ((int*)vals)[tid];
    __syncthreads();

    float u = ((float)(r + 1) + 0.5f) * (1.0f / (float)L_);
    u = fminf(fmaxf(u, 1e-6f), 1.0f - 1e-6f);
    float zv = erfinvf(2.0f * u - 1.0f) * 1.41421356237309515f;
    g_zh[(size_t)blk * L_ + tid] = __float2half(zv);

    vals[tid] = zv;
    sq[tid] = zv * zv;
    __syncthreads();
    for (int s = 512; s > 0; s >>= 1) {
        if (tid < s) { vals[tid] += vals[tid + s]; sq[tid] += sq[tid + s]; }
        __syncthreads();
    }
    if (tid == 0) {
        float sum = vals[0], ssq = sq[0];
        float mean = sum * (1.0f / (float)L_);
        float var = (ssq - sum * sum * (1.0f / (float)L_)) * (1.0f / (float)(L_ - 1));
        int b = blk / D_, d = blk % D_;
        g_s[b * 2 * D_ + d] = mean;
        g_s[b * 2 * D_ + D_ + d] = sqrtf(fmaxf(var, 0.0f));
    }
}

// ---------------- s -> relu(mlp1) -> relu(mlp2) -> g_h2 ----------------
__global__ void mlp12_kernel(const float* __restrict__ w1, const float* __restrict__ b1,
                             const float* __restrict__ w2, const float* __restrict__ b2) {
    __shared__ float srow[2 * D_];
    __shared__ float h1[64];
    int b = blockIdx.x, tid = threadIdx.x;
    for (int i = tid; i < 2 * D_; i += 64) srow[i] = g_s[b * 2 * D_ + i];
    __syncthreads();
    float acc = b1[tid];
    for (int k = 0; k < 2 * D_; ++k) acc += srow[k] * w1[tid * 2 * D_ + k];
    h1[tid] = fmaxf(acc, 0.0f);
    __syncthreads();
    if (tid < 32) {
        float a2 = b2[tid];
        for (int k = 0; k < 64; ++k) a2 += h1[k] * w2[tid * 64 + k];
        g_h2[b * 32 + tid] = fmaxf(a2, 0.0f);
    }
}

// ---------------- lower = h2 @ mlp3_w^T + b ----------------
__global__ __launch_bounds__(256) void lower_kernel(const float* __restrict__ w3,
                                                    const float* __restrict__ b3) {
    __shared__ float h2s[32];
    __shared__ float wt[256][33];
    int b = blockIdx.x;
    int j0 = blockIdx.y * 256;
    int tid = threadIdx.x;
    if (tid < 32) h2s[tid] = g_h2[b * 32 + tid];
    for (int i = tid; i < 256 * 32; i += 256) {
        int rr = i >> 5, cc = i & 31;
        wt[rr][cc] = w3[(size_t)j0 * 32 + i];
    }
    __syncthreads();
    float acc = b3[j0 + tid];
#pragma unroll
    for (int k = 0; k < 32; ++k) acc += h2s[k] * wt[tid][k];
    g_lower[(size_t)b * (D_ * M_) + j0 + tid] = acc;
}

// ---------------- lam[b] = lower[b] @ lower[b]^T  (into d_out) ----------------
__global__ __launch_bounds__(256) void lam_kernel(float* __restrict__ lam_out) {
    extern __shared__ float low[];   // [128][129]
    int b = blockIdx.x, tid = threadIdx.x;
    for (int i = tid; i < D_ * M_; i += 256) {
        int rr = i >> 7, cc = i & 127;
        low[rr * 129 + cc] = g_lower[(size_t)b * (D_ * M_) + i];
    }
    __syncthreads();
    for (int e = tid; e < D_ * D_; e += 256) {
        int i = e >> 7, j = e & 127;
        const float* ri = &low[i * 129];
        const float* rj = &low[j * 129];
        float acc = 0.0f;
#pragma unroll 8
        for (int m = 0; m < M_; ++m) acc += ri[m] * rj[m];
        lam_out[(size_t)b * D_ * D_ + e] = acc;
    }
}

// ================= pipelined mma.sync fp16 NT GEMM =================
// 128x128 CTA tile, warp grid 2x4 (warp tile 64x32). K-chunk 64 (128B rows, SW128).
// TT: lo-fragment ldsm hoisted ahead of the hi-mma batch so its latency is covered
// by the 8 hi-mmas. Per-accumulator order unchanged (hi then lo) -> bit-identical.
#define GDYN 99328
template<int TT>
__global__ __launch_bounds__(256, 2) void gemm_mma_kernel(
    const __half* __restrict__ Ah,
    const __half* __restrict__ Whi, const __half* __restrict__ Wlo,
    const float* __restrict__ bias, float* __restrict__ C,
    __half* __restrict__ Ch,
    int Ndim, int Kdim, int relu, int writeC)
{
    constexpr int NSTG = TT ? 2 : 3;
    constexpr int STG = TT ? 49152 : 32768;
    constexpr int TOT = TT ? 3072 : 2048;   // 16B segs per stage

    extern __shared__ char dsm_raw[];
    uint32_t dsm_u0 = smem_to_u32(dsm_raw);
    uint32_t base_u = (dsm_u0 + 1023u) & ~1023u;
    int tid = threadIdx.x;
    int wid = tid >> 5, lane = tid & 31;
    int n0 = blockIdx.x * 128, m0 = blockIdx.y * 128;
    int wm = (wid >> 2) * 64;    // 2 warp rows
    int wn = (wid & 3) * 32;     // 4 warp cols

    float acc[4][4][4];
#pragma unroll
    for (int a = 0; a < 4; ++a)
#pragma unroll
        for (int b = 0; b < 4; ++b)
#pragma unroll
            for (int c = 0; c < 4; ++c) acc[a][b][c] = 0.0f;

    int nch = Kdim >> 6;

    auto stage_fill = [&](int ch, int stg) {
        int k0 = ch << 6;
        uint32_t sb = base_u + stg * STG;
#pragma unroll
        for (int t = 0; t < TOT / 256; ++t) {
            int i = tid + t * 256;
            int tensor = i >> 10;            // 0=A, 1=Whi, 2=Wlo
            int r = (i >> 3) & 127;
            int cs = i & 7;
            const __half* g = (tensor == 0) ? Ah : ((tensor == 1) ? Whi : Wlo);
            int rr = ((tensor == 0) ? m0 : n0) + r;
            g += (size_t)rr * Kdim + k0 + cs * 8;
            uint32_t off = (uint32_t)(r * 128 + cs * 16);
            uint32_t sw = off ^ ((off >> 3) & 0x70);
            cp_async16(sb + tensor * 16384 + sw, g);
        }
        cp_commit();
    };

    if (TT) {
        stage_fill(0, 0);
    } else {
        stage_fill(0, 0);
        stage_fill(1, 1);
    }

    // hoisted ldsm address components (XOR mask depends only on lane&7)
    uint32_t xm = (uint32_t)(lane & 7) << 4;
    uint32_t a_base = (uint32_t)((wm + (lane & 15)) * 128 + ((lane >> 4) << 4));
    uint32_t w_base = (uint32_t)((wn + ((lane >> 3) & 1) * 8 + (lane & 7)) * 128
                                 + ((lane >> 4) << 4));

    for (int ch = 0; ch < nch; ++ch) {
        if (TT) {
            cp_wait<0>();
        } else {
            if (ch <= nch - 2) cp_wait<1>(); else cp_wait<0>();
        }
        __syncthreads();
        if (TT) {
            if (ch + 1 < nch) stage_fill(ch + 1, (ch + 1) & 1);
        } else {
            if (ch + 2 < nch) stage_fill(ch + 2, (ch + 2) % 3);
        }

        uint32_t sb = base_u + (ch % NSTG) * STG;
#pragma unroll
        for (int s = 0; s < 4; ++s) {
            uint32_t af[4][4];
#pragma unroll
            for (int mt = 0; mt < 4; ++mt)
                ldsm_x4(af[mt][0], af[mt][1], af[mt][2], af[mt][3],
                        sb + ((a_base + mt * 2048 + s * 32) ^ xm));
#pragma unroll
            for (int g16 = 0; g16 < 2; ++g16) {
                uint32_t wadr = (w_base + g16 * 2048 + s * 32) ^ xm;
                uint32_t h[4];
                ldsm_x4(h[0], h[1], h[2], h[3], sb + 16384 + wadr);
                if (TT) {
                    // lo fragment loaded BEFORE hi mmas: latency covered by them
                    uint32_t l[4];
                    ldsm_x4(l[0], l[1], l[2], l[3], sb + 32768 + wadr);
#pragma unroll
                    for (int mt = 0; mt < 4; ++mt) {
                        mma_f16(acc[mt][2 * g16],     af[mt], h[0], h[2]);
                        mma_f16(acc[mt][2 * g16 + 1], af[mt], h[1], h[3]);
                    }
#pragma unroll
                    for (int mt = 0; mt < 4; ++mt) {
                        mma_f16(acc[mt][2 * g16],     af[mt], l[0], l[2]);
                        mma_f16(acc[mt][2 * g16 + 1], af[mt], l[1], l[3]);
                    }
                } else {
#pragma unroll
                    for (int mt = 0; mt < 4; ++mt) {
                        mma_f16(acc[mt][2 * g16],     af[mt], h[0], h[2]);
                        mma_f16(acc[mt][2 * g16 + 1], af[mt], h[1], h[3]);
                    }
                }
            }
        }
    }

    int r4 = lane >> 2, c2 = (lane & 3) * 2;
#pragma unroll
    for (int mt = 0; mt < 4; ++mt) {
        int row0 = m0 + wm + mt * 16 + r4;
#pragma unroll
        for (int nb = 0; nb < 4; ++nb) {
            int col = n0 + wn + nb * 8 + c2;
            float bx = bias[col], by = bias[col + 1];
            float2 v0 = {acc[mt][nb][0] + bx, acc[mt][nb][1] + by};
            float2 v1 = {acc[mt][nb][2] + bx, acc[mt][nb][3] + by};
            if (relu) {
                v0.x = fmaxf(v0.x, 0.f); v0.y = fmaxf(v0.y, 0.f);
                v1.x = fmaxf(v1.x, 0.f); v1.y = fmaxf(v1.y, 0.f);
            }
            size_t i0 = (size_t)row0 * Ndim + col;
            size_t i1 = (size_t)(row0 + 8) * Ndim + col;
            if (writeC) {
                *(float2*)&C[i0] = v0;
                *(float2*)&C[i1] = v1;
            }
            if (Ch) {
                *(__half2*)&Ch[i0] = __half2(__float2half(v0.x), __float2half(v0.y));
                *(__half2*)&Ch[i1] = __half2(__float2half(v1.x), __float2half(v1.y));
            }
        }
    }
}

// ---------------- fused attention per (b,h), 256 threads, f32x2, register scores ----------------
#define KROW 68
#define CBROW 36
#define ATTN_SMEM ((128 * KROW * 2 + 128 * CBROW) * 4)
__global__ __launch_bounds__(256, 2) void attn_kernel() {
    extern __shared__ float sm[];
    float* ks = sm;
    float* vs = sm + 128 * KROW;
    float* cb = sm + 2 * 128 * KROW;

    int bh = blockIdx.x;
    int b = bh >> 3, h = bh & 7;
    int tid = threadIdx.x;
    int row = tid & 127, jh = tid >> 7;
    const float* qkvb = g_qkv + (size_t)b * D_ * 3 * DM_;

    const float* krow = qkvb + (size_t)row * 3 * DM_ + DM_ + h * DH_ + jh * 32;
    const float* vrow = qkvb + (size_t)row * 3 * DM_ + 2 * DM_ + h * DH_ + jh * 32;
#pragma unroll
    for (int c = 0; c < 32; c += 4) {
        *(float4*)&ks[row * KROW + jh * 32 + c] = *(const float4*)(krow + c);
        *(float4*)&vs[row * KROW + jh * 32 + c] = *(const float4*)(vrow + c);
    }
    __syncthreads();

    float s[64];
    const float* qrow = qkvb + (size_t)row * 3 * DM_ + h * DH_;
#pragma unroll
    for (int ch2 = 0; ch2 < 2; ++ch2) {
        u64t q2[16];
        const u64t* q64 = (const u64t*)(qrow + ch2 * 32);
#pragma unroll
        for (int c = 0; c < 16; ++c) q2[c] = q64[c];
#pragma unroll 4
        for (int j0 = 0; j0 < 64; ++j0) {
            int jg = jh * 64 + j0;
            const u64t* k64 = (const u64t*)&ks[jg * KROW + ch2 * 32];
            u64t a2 = pk2(0.f, 0.f);
#pragma unroll
            for (int c = 0; c < 16; ++c) a2 = fma2(q2[c], k64[c], a2);
            float ax, ay; upk2(a2, ax, ay);
            s[j0] = (ch2 ? s[j0] : 0.0f) + ax + ay;
        }
    }
    float mx = -1e30f;
#pragma unroll
    for (int j = 0; j < 64; ++j) { s[j] *= 0.125f; mx = fmaxf(mx, s[j]); }
    cb[jh * 128 + row] = mx;
    __syncthreads();
    mx = fmaxf(cb[row], cb[128 + row]);
    float lsum = 0.0f;
#pragma unroll
    for (int j = 0; j < 64; ++j) { s[j] = __expf(s[j] - mx); lsum += s[j]; }
    cb[256 + jh * 128 + row] = lsum;
    __syncthreads();
    float inv = 1.0f / (cb[256 + row] + cb[384 + row]);
#pragma unroll
    for (int j = 0; j < 64; ++j) s[j] *= inv;

#pragma unroll
    for (int cp = 0; cp < 2; ++cp) {
        u64t a2[16];
#pragma unroll
        for (int c = 0; c < 16; ++c) a2[c] = pk2(0.f, 0.f);
#pragma unroll 4
        for (int j0 = 0; j0 < 64; ++j0) {
            int jg = jh * 64 + j0;
            u64t p2 = pk2(s[j0], s[j0]);
            const u64t* v64 = (const u64t*)&vs[jg * KROW + cp * 32];
#pragma unroll
            for (int c = 0; c < 16; ++c) a2[c] = fma2(p2, v64[c], a2[c]);
        }
        __syncthreads();
        if (jh == 0) {
#pragma unroll
            for (int c = 0; c < 16; ++c) {
                float ax, ay; upk2(a2[c], ax, ay);
                cb[row * CBROW + 2 * c] = ax;
                cb[row * CBROW + 2 * c + 1] = ay;
            }
        }
        __syncthreads();
        if (jh == 1) {
            size_t obase = ((size_t)b * D_ + row) * DM_ + h * DH_ + cp * 32;
#pragma unroll
            for (int c = 0; c < 16; ++c) {
                float ax, ay; upk2(a2[c], ax, ay);
                float fx = ax + cb[row * CBROW + 2 * c];
                float fy = ay + cb[row * CBROW + 2 * c + 1];
                *(__half2*)&g_ctxh[obase + 2 * c] = __floats2half2_rn(fx, fy);
            }
        }
    }
}

// ---------------- residual + layernorm, float4 vectorized ----------------
__global__ __launch_bounds__(128) void resid_ln_kernel(const float* __restrict__ y,
                                                       const float* __restrict__ gam,
                                                       const float* __restrict__ bet,
                                                       int has_res) {
    int row = blockIdx.x, tid = threadIdx.x;
    float* trow = g_t + (size_t)row * DM_;
    float4 tv = *(float4*)&trow[tid * 4];
    if (has_res) {
        float4 yv = *(const float4*)&y[(size_t)row * DM_ + tid * 4];
        tv.x += yv.x; tv.y += yv.y; tv.z += yv.z; tv.w += yv.w;
    }
    float s = tv.x + tv.y + tv.z + tv.w;
    float sq = tv.x * tv.x + tv.y * tv.y + tv.z * tv.z + tv.w * tv.w;
    __shared__ float rs[4], rq[4];
    unsigned lane = tid & 31, wid = tid >> 5;
#pragma unroll
    for (int off = 16; off; off >>= 1) {
        s += __shfl_down_sync(0xffffffffu, s, off);
        sq += __shfl_down_sync(0xffffffffu, sq, off);
    }
    if (lane == 0) { rs[wid] = s; rq[wid] = sq; }
    __syncthreads();
    float S = rs[0] + rs[1] + rs[2] + rs[3];
    float SQ = rq[0] + rq[1] + rq[2] + rq[3];
    float mean = S * (1.0f / (float)DM_);
    float var = SQ * (1.0f / (float)DM_) - mean * mean;
    float rstd = rsqrtf(var + 1e-5f);
    float4 g4 = *(const float4*)&gam[tid * 4];
    float4 b4 = *(const float4*)&bet[tid * 4];
    float4 o;
    o.x = (tv.x - mean) * rstd * g4.x + b4.x;
    o.y = (tv.y - mean) * rstd * g4.y + b4.y;
    o.z = (tv.z - mean) * rstd * g4.z + b4.z;
    o.w = (tv.w - mean) * rstd * g4.w + b4.w;
    *(float4*)&trow[tid * 4] = o;
    __half2* thp = (__half2*)&g_th[(size_t)row * DM_ + tid * 4];
    thp[0] = __floats2half2_rn(o.x, o.y);
    thp[1] = __floats2half2_rn(o.z, o.w);
}

// ---------------- head ----------------
__global__ __launch_bounds__(128) void head_kernel(const float* __restrict__ u,
                                                   const float* __restrict__ head_bias,
                                                   const float* __restrict__ lam,
                                                   float* __restrict__ out_y) {
    __shared__ float hps[M_];
    __shared__ float red[4];
    __shared__ float ybc;
    int blk = blockIdx.x;
    int b = blk >> 7, i = blk & 127;
    int tid = threadIdx.x;
    hps[tid] = g_hp[(size_t)blk * M_ + tid];
    __syncthreads();
    const float* lamb = lam + (size_t)b * D_ * D_;
    float acc = 0.0f;
    for (int k = 0; k < D_; ++k) acc += hps[k] * lamb[(size_t)k * D_ + tid];
    float p = acc * u[(size_t)i * M_ + tid];
    unsigned lane = tid & 31, wid = tid >> 5;
#pragma unroll
    for (int off = 16; off; off >>= 1) p += __shfl_down_sync(0xffffffffu, p, off);
    if (lane == 0) red[wid] = p;
    __syncthreads();
    if (tid == 0) ybc = red[0] + red[1] + red[2] + red[3] + head_bias[i];
    __syncthreads();
    float yv = ybc;
    if (tid < PRED_) out_y[(size_t)blk * PRED_ + tid] = yv;
}

// ---------------- host launcher ----------------
extern "C" void kernel_launch(void* const* d_in, const int* in_sizes, int n_in,
                              void* d_out, int out_size) {
    const float* x      = (const float*)d_in[0];
    const float* emb_w  = (const float*)d_in[1];
    const float* emb_b  = (const float*)d_in[2];
    const float* qkv_w  = (const float*)d_in[3];
    const float* qkv_b  = (const float*)d_in[4];
    const float* out_w  = (const float*)d_in[5];
    const float* out_b  = (const float*)d_in[6];
    const float* ln1_g  = (const float*)d_in[7];
    const float* ln1_b  = (const float*)d_in[8];
    const float* ln2_g  = (const float*)d_in[9];
    const float* ln2_b  = (const float*)d_in[10];
    const float* ff1_w  = (const float*)d_in[11];
    const float* ff1_b  = (const float*)d_in[12];
    const float* ff2_w  = (const float*)d_in[13];
    const float* ff2_b  = (const float*)d_in[14];
    const float* fn_g   = (const float*)d_in[15];
    const float* fn_b   = (const float*)d_in[16];
    const float* mlp1_w = (const float*)d_in[17];
    const float* mlp1_b = (const float*)d_in[18];
    const float* mlp2_w = (const float*)d_in[19];
    const float* mlp2_b = (const float*)d_in[20];
    const float* mlp3_w = (const float*)d_in[21];
    const float* mlp3_b = (const float*)d_in[22];
    const float* proj_w = (const float*)d_in[23];
    const float* proj_b = (const float*)d_in[24];
    const float* u      = (const float*)d_in[25];
    const float* hbias  = (const float*)d_in[26];

    float* out = (float*)d_out;
    float* out_lam = out + (size_t)B_ * D_ * PRED_;
    float* out_u = out_lam + (size_t)B_ * D_ * D_;

    float *t, *qkv, *y, *hp;
    __half *zh, *th, *ch, *mh, *whi, *wlo;
    cudaGetSymbolAddress((void**)&t, g_t);
    cudaGetSymbolAddress((void**)&qkv, g_qkv);
    cudaGetSymbolAddress((void**)&y, g_y);
    cudaGetSymbolAddress((void**)&hp, g_hp);
    cudaGetSymbolAddress((void**)&zh, g_zh);
    cudaGetSymbolAddress((void**)&th, g_th);
    cudaGetSymbolAddress((void**)&ch, g_ctxh);
    cudaGetSymbolAddress((void**)&mh, g_midh);
    cudaGetSymbolAddress((void**)&whi, g_whi);
    cudaGetSymbolAddress((void**)&wlo, g_wlo);

    cudaFuncSetAttribute(lam_kernel, cudaFuncAttributeMaxDynamicSharedMemorySize, 128 * 129 * 4);
    cudaFuncSetAttribute(attn_kernel, cudaFuncAttributeMaxDynamicSharedMemorySize, ATTN_SMEM);
    cudaFuncSetAttribute((void*)gemm_mma_kernel<1>,
                         cudaFuncAttributeMaxDynamicSharedMemorySize, GDYN);
    cudaFuncSetAttribute((void*)gemm_mma_kernel<0>,
                         cudaFuncAttributeMaxDynamicSharedMemorySize, GDYN);

    const int ROWS = B_ * D_;   // 8192

    // launches 1-3: prerequisites of the emb GEMM
    cvt_all_kernel<<<(2244608 + 255) / 256, 256>>>(emb_w, qkv_w, out_w, ff1_w, ff2_w, proj_w);
    transpose_x_kernel<<<dim3(L_ / 32, D_ / 32, B_), dim3(32, 8)>>>(x);
    copula_kernel<<<B_ * D_, 1024>>>();

    // launch 4: emb GEMM (profiled by ncu's bounded capture)
    gemm_mma_kernel<1><<<dim3(DM_ / 128, ROWS / 128), 256, GDYN>>>(
        zh, whi + OFF_EMB, wlo + OFF_EMB, emb_b, t, th, DM_, L_, 0, 1);

    // factor chain
    mlp12_kernel<<<B_, 64>>>(mlp1_w, mlp1_b, mlp2_w, mlp2_b);
    lower_kernel<<<dim3(B_, (D_ * M_) / 256), 256>>>(mlp3_w, mlp3_b);
    lam_kernel<<<B_, 256, 128 * 129 * 4>>>(out_lam);

    for (int l = 0; l < NL_; ++l) {
        gemm_mma_kernel<1><<<dim3(3 * DM_ / 128, ROWS / 128), 256, GDYN>>>(
            th, whi + OFF_QKV + (size_t)l * 3 * DM_ * DM_,
            wlo + OFF_QKV + (size_t)l * 3 * DM_ * DM_, qkv_b + (size_t)l * 3 * DM_,
            qkv, nullptr, 3 * DM_, DM_, 0, 1);
        attn_kernel<<<B_ * H_, 256, ATTN_SMEM>>>();
        gemm_mma_kernel<1><<<dim3(DM_ / 128, ROWS / 128), 256, GDYN>>>(
            ch, whi + OFF_OUT + (size_t)l * DM_ * DM_,
            wlo + OFF_OUT + (size_t)l * DM_ * DM_, out_b + (size_t)l * DM_,
            y, nullptr, DM_, DM_, 0, 1);
        resid_ln_kernel<<<ROWS, 128>>>(y, ln1_g + l * DM_, ln1_b + l * DM_, 1);
        gemm_mma_kernel<0><<<dim3(2 * DM_ / 128, ROWS / 128), 256, GDYN>>>(
            th, whi + OFF_FF1 + (size_t)l * 2 * DM_ * DM_,
            wlo + OFF_FF1 + (size_t)l * 2 * DM_ * DM_, ff1_b + (size_t)l * 2 * DM_,
            nullptr, mh, 2 * DM_, DM_, 1, 0);
        gemm_mma_kernel<0><<<dim3(DM_ / 128, ROWS / 128), 256, GDYN>>>(
            mh, whi + OFF_FF2 + (size_t)l * DM_ * 2 * DM_,
            wlo + OFF_FF2 + (size_t)l * DM_ * 2 * DM_, ff2_b + (size_t)l * DM_,
            y, nullptr, DM_, 2 * DM_, 0, 1);
        resid_ln_kernel<<<ROWS, 128>>>(y, ln2_g + l * DM_, ln2_b + l * DM_, 1);
    }

    resid_ln_kernel<<<ROWS, 128>>>(y, fn_g, fn_b, 0);

    gemm_mma_kernel<1><<<dim3(M_ / 128, ROWS / 128), 256, GDYN>>>(
        th, whi + OFF_PROJ, wlo + OFF_PROJ, proj_b, hp, nullptr, M_, DM_, 0, 1);
    head_kernel<<<ROWS, 128>>>(u, hbias, out_lam, out);

    cudaMemcpyAsync(out_u, u, (size_t)D_ * M_ * sizeof(float), cudaMemcpyDeviceToDevice);
}

// round 17
// speedup vs baseline: 1.0290x; 1.0290x over previous
#include <cuda_runtime.h>
#include <cuda_fp16.h>
#include <cstdint>
#include <math.h>

#define B_    64
#define L_    1024
#define D_    128
#define M_    128
#define DM_   512
#define NL_   4
#define H_    8
#define DH_   64
#define PRED_ 96

// ================= helpers =================
__device__ __forceinline__ uint32_t smem_to_u32(const void* smem_ptr) {
    uint32_t addr;
    asm("{ .reg .u64 tmp; cvta.to.shared.u64 tmp, %1; cvt.u32.u64 %0, tmp; }"
        : "=r"(addr) : "l"(smem_ptr));
    return addr;
}
__device__ __forceinline__ void ldsm_x4(uint32_t& r0, uint32_t& r1, uint32_t& r2,
                                        uint32_t& r3, uint32_t addr) {
    asm volatile("ldmatrix.sync.aligned.m8n8.x4.shared.b16 {%0,%1,%2,%3}, [%4];"
                 : "=r"(r0), "=r"(r1), "=r"(r2), "=r"(r3) : "r"(addr));
}
__device__ __forceinline__ void mma_f16(float* d, const uint32_t* a, uint32_t b0, uint32_t b1) {
    asm volatile(
        "mma.sync.aligned.m16n8k16.row.col.f32.f16.f16.f32 "
        "{%0,%1,%2,%3}, {%4,%5,%6,%7}, {%8,%9}, {%0,%1,%2,%3};"
        : "+f"(d[0]), "+f"(d[1]), "+f"(d[2]), "+f"(d[3])
        : "r"(a[0]), "r"(a[1]), "r"(a[2]), "r"(a[3]), "r"(b0), "r"(b1));
}
__device__ __forceinline__ void cp_async16(uint32_t saddr, const void* gptr) {
    asm volatile("cp.async.cg.shared.global [%0], [%1], 16;" :: "r"(saddr), "l"(gptr));
}
__device__ __forceinline__ void cp_commit() {
    asm volatile("cp.async.commit_group;" ::: "memory");
}
template<int N> __device__ __forceinline__ void cp_wait() {
    asm volatile("cp.async.wait_group %0;" :: "n"(N) : "memory");
}
// packed fp32x2
typedef unsigned long long u64t;
__device__ __forceinline__ u64t pk2(float a, float b) {
    u64t r; asm("mov.b64 %0, {%1, %2};" : "=l"(r) : "f"(a), "f"(b)); return r;
}
__device__ __forceinline__ void upk2(u64t x, float& a, float& b) {
    asm("mov.b64 {%0, %1}, %2;" : "=f"(a), "=f"(b) : "l"(x));
}
__device__ __forceinline__ u64t fma2(u64t a, u64t b, u64t c) {
    u64t d; asm("fma.rn.f32x2 %0, %1, %2, %3;" : "=l"(d) : "l"(a), "l"(b), "l"(c));
    return d;
}

// ---------------- scratch (device globals; no allocation) ----------------
__device__ float g_xt[(size_t)B_ * D_ * L_];
__device__ float g_s[B_ * 2 * D_];
__device__ float g_h2[B_ * 32];
__device__ float g_lower[(size_t)B_ * D_ * M_];
__device__ float g_t[(size_t)B_ * D_ * DM_];
__device__ float g_qkv[(size_t)B_ * D_ * 3 * DM_];
__device__ float g_y[(size_t)B_ * D_ * DM_];
__device__ float g_hp[(size_t)B_ * D_ * M_];

// fp16 single activation buffers
__device__ __half g_zh[(size_t)B_ * D_ * L_];
__device__ __half g_th[(size_t)B_ * D_ * DM_];
__device__ __half g_ctxh[(size_t)B_ * D_ * DM_];
__device__ __half g_midh[(size_t)B_ * D_ * 2 * DM_];

// fp16 hi/lo weight buffers (packed)
#define OFF_EMB  0
#define OFF_QKV  524288
#define OFF_OUT  3670016
#define OFF_FF1  4718592
#define OFF_FF2  6815744
#define OFF_PROJ 8912896
#define W_TOTAL  8978432
__device__ __half g_whi[W_TOTAL];
__device__ __half g_wlo[W_TOTAL];

// ---------------- all-weights fp32 -> (hi, lo) fp16 conversion (one launch) ----------------
__global__ void cvt_all_kernel(const float* __restrict__ s0, const float* __restrict__ s1,
                               const float* __restrict__ s2, const float* __restrict__ s3,
                               const float* __restrict__ s4, const float* __restrict__ s5) {
    int gid = blockIdx.x * 256 + threadIdx.x;
    if (gid >= 2244608) return;
    const float* src; size_t off; int local;
    if (gid < 131072)       { src = s0; off = OFF_EMB;  local = gid; }
    else if (gid < 917504)  { src = s1; off = OFF_QKV;  local = gid - 131072; }
    else if (gid < 1179648) { src = s2; off = OFF_OUT;  local = gid - 917504; }
    else if (gid < 1703936) { src = s3; off = OFF_FF1;  local = gid - 1179648; }
    else if (gid < 2228224) { src = s4; off = OFF_FF2;  local = gid - 1703936; }
    else                    { src = s5; off = OFF_PROJ; local = gid - 2228224; }
    float4 f = ((const float4*)src)[local];
    __half h0 = __float2half(f.x), h1 = __float2half(f.y);
    __half h2 = __float2half(f.z), h3 = __float2half(f.w);
    __half2* hp = (__half2*)(g_whi + off);
    __half2* lp = (__half2*)(g_wlo + off);
    hp[2 * local] = __half2(h0, h1);
    hp[2 * local + 1] = __half2(h2, h3);
    lp[2 * local] = __half2(__float2half(f.x - __half2float(h0)),
                            __float2half(f.y - __half2float(h1)));
    lp[2 * local + 1] = __half2(__float2half(f.z - __half2float(h2)),
                                __float2half(f.w - __half2float(h3)));
}

// ---------------- transpose x [B,L,D] -> g_xt [B,D,L] ----------------
__global__ void transpose_x_kernel(const float* __restrict__ x) {
    __shared__ float tile[32][33];
    int b = blockIdx.z;
    int l0 = blockIdx.x * 32, d0 = blockIdx.y * 32;
    int lx = threadIdx.x, ly = threadIdx.y;
#pragma unroll
    for (int r = 0; r < 32; r += 8)
        tile[ly + r][lx] = x[((size_t)b * L_ + (l0 + ly + r)) * D_ + (d0 + lx)];
    __syncthreads();
#pragma unroll
    for (int r = 0; r < 32; r += 8)
        g_xt[((size_t)b * D_ + (d0 + ly + r)) * L_ + (l0 + lx)] = tile[lx][ly + r];
}

// ---------------- copula: u64-key hybrid bitonic rank -> erfinv z (fp16) ----------------
__global__ __launch_bounds__(1024) void copula_kernel() {
    __shared__ u64t keys[L_];
    __shared__ float vals[L_];
    __shared__ float sq[L_];

    int blk = blockIdx.x;
    int tid = threadIdx.x;

    uint32_t fb = __float_as_uint(g_xt[(size_t)blk * L_ + tid]);
    uint32_t mk = fb ^ ((fb & 0x80000000u) ? 0xFFFFFFFFu : 0x80000000u);
    u64t key = ((u64t)mk << 32) | (uint32_t)tid;

#pragma unroll
    for (int k = 2; k <= 32; k <<= 1) {
#pragma unroll
        for (int j = k >> 1; j > 0; j >>= 1) {
            u64t ko = __shfl_xor_sync(0xffffffffu, key, j);
            bool keepmin = (((tid & k) == 0) == ((tid & j) == 0));
            u64t mn = key < ko ? key : ko;
            u64t mx = key < ko ? ko : key;
            key = keepmin ? mn : mx;
        }
    }
    for (int k = 64; k <= 1024; k <<= 1) {
        keys[tid] = key;
        __syncthreads();
        for (int j = k >> 1; j >= 32; j >>= 1) {
            int ixj = tid ^ j;
            if (ixj > tid) {
                u64t a = keys[tid], b = keys[ixj];
                if ((a > b) == ((tid & k) == 0)) { keys[tid] = b; keys[ixj] = a; }
            }
            __syncthreads();
        }
        key = keys[tid];
#pragma unroll
        for (int j = 16; j > 0; j >>= 1) {
            u64t ko = __shfl_xor_sync(0xffffffffu, key, j);
            bool keepmin = (((tid & k) == 0) == ((tid & j) == 0));
            u64t mn = key < ko ? key : ko;
            u64t mx = key < ko ? ko : key;
            key = keepmin ? mn : mx;
        }
    }
    __syncthreads();
    ((int*)vals)[(uint32_t)(key & 0xFFFFFFFFu)] = tid;
    __syncthreads();
    int r = ((int*)vals)[tid];
    __syncthreads();

    float u = ((float)(r + 1) + 0.5f) * (1.0f / (float)L_);
    u = fminf(fmaxf(u, 1e-6f), 1.0f - 1e-6f);
    float zv = erfinvf(2.0f * u - 1.0f) * 1.41421356237309515f;
    g_zh[(size_t)blk * L_ + tid] = __float2half(zv);

    vals[tid] = zv;
    sq[tid] = zv * zv;
    __syncthreads();
    for (int s = 512; s > 0; s >>= 1) {
        if (tid < s) { vals[tid] += vals[tid + s]; sq[tid] += sq[tid + s]; }
        __syncthreads();
    }
    if (tid == 0) {
        float sum = vals[0], ssq = sq[0];
        float mean = sum * (1.0f / (float)L_);
        float var = (ssq - sum * sum * (1.0f / (float)L_)) * (1.0f / (float)(L_ - 1));
        int b = blk / D_, d = blk % D_;
        g_s[b * 2 * D_ + d] = mean;
        g_s[b * 2 * D_ + D_ + d] = sqrtf(fmaxf(var, 0.0f));
    }
}

// ---------------- s -> relu(mlp1) -> relu(mlp2) -> g_h2 ----------------
__global__ void mlp12_kernel(const float* __restrict__ w1, const float* __restrict__ b1,
                             const float* __restrict__ w2, const float* __restrict__ b2) {
    __shared__ float srow[2 * D_];
    __shared__ float h1[64];
    int b = blockIdx.x, tid = threadIdx.x;
    for (int i = tid; i < 2 * D_; i += 64) srow[i] = g_s[b * 2 * D_ + i];
    __syncthreads();
    float acc = b1[tid];
    for (int k = 0; k < 2 * D_; ++k) acc += srow[k] * w1[tid * 2 * D_ + k];
    h1[tid] = fmaxf(acc, 0.0f);
    __syncthreads();
    if (tid < 32) {
        float a2 = b2[tid];
        for (int k = 0; k < 64; ++k) a2 += h1[k] * w2[tid * 64 + k];
        g_h2[b * 32 + tid] = fmaxf(a2, 0.0f);
    }
}

// ---------------- lower = h2 @ mlp3_w^T + b ----------------
__global__ __launch_bounds__(256) void lower_kernel(const float* __restrict__ w3,
                                                    const float* __restrict__ b3) {
    __shared__ float h2s[32];
    __shared__ float wt[256][33];
    int b = blockIdx.x;
    int j0 = blockIdx.y * 256;
    int tid = threadIdx.x;
    if (tid < 32) h2s[tid] = g_h2[b * 32 + tid];
    for (int i = tid; i < 256 * 32; i += 256) {
        int rr = i >> 5, cc = i & 31;
        wt[rr][cc] = w3[(size_t)j0 * 32 + i];
    }
    __syncthreads();
    float acc = b3[j0 + tid];
#pragma unroll
    for (int k = 0; k < 32; ++k) acc += h2s[k] * wt[tid][k];
    g_lower[(size_t)b * (D_ * M_) + j0 + tid] = acc;
}

// ---------------- lam[b] = lower[b] @ lower[b]^T  (into d_out) ----------------
__global__ __launch_bounds__(256) void lam_kernel(float* __restrict__ lam_out) {
    extern __shared__ float low[];   // [128][129]
    int b = blockIdx.x, tid = threadIdx.x;
    for (int i = tid; i < D_ * M_; i += 256) {
        int rr = i >> 7, cc = i & 127;
        low[rr * 129 + cc] = g_lower[(size_t)b * (D_ * M_) + i];
    }
    __syncthreads();
    for (int e = tid; e < D_ * D_; e += 256) {
        int i = e >> 7, j = e & 127;
        const float* ri = &low[i * 129];
        const float* rj = &low[j * 129];
        float acc = 0.0f;
#pragma unroll 8
        for (int m = 0; m < M_; ++m) acc += ri[m] * rj[m];
        lam_out[(size_t)b * D_ * D_ + e] = acc;
    }
}

// ================= pipelined mma.sync fp16 NT GEMM =================
// CTA tile 128x64, 8 warps in 4x2, warp tile 32x32 -> acc 32 regs -> 3 CTAs/SM
// (6 warps/SMSP for latency hiding). K-chunk 64 (128B rows, SW128 swizzle).
// stage: A 16KB @0, Whi 8KB @16384, Wlo 8KB @24576. TT: 2 stages x 32KB; 1-term: 3 x 24KB.
// Per-element accumulation order unchanged (k16 in order, hi then lo) -> bit-identical.
#define GDYN 74752
template<int TT>
__global__ __launch_bounds__(256, 3) void gemm_mma_kernel(
    const __half* __restrict__ Ah,
    const __half* __restrict__ Whi, const __half* __restrict__ Wlo,
    const float* __restrict__ bias, float* __restrict__ C,
    __half* __restrict__ Ch,
    int Ndim, int Kdim, int relu, int writeC)
{
    constexpr int NSTG = TT ? 2 : 3;
    constexpr int STG = TT ? 32768 : 24576;
    constexpr int TOT = TT ? 2048 : 1536;   // 16B segs per stage

    extern __shared__ char dsm_raw[];
    uint32_t dsm_u0 = smem_to_u32(dsm_raw);
    uint32_t base_u = (dsm_u0 + 1023u) & ~1023u;
    int tid = threadIdx.x;
    int wid = tid >> 5, lane = tid & 31;
    int n0 = blockIdx.x * 64, m0 = blockIdx.y * 128;
    int wm = (wid >> 1) * 32;    // 4 warp rows of 32
    int wn = (wid & 1) * 32;     // 2 warp cols of 32

    float acc[2][4][4];
#pragma unroll
    for (int a = 0; a < 2; ++a)
#pragma unroll
        for (int b = 0; b < 4; ++b)
#pragma unroll
            for (int c = 0; c < 4; ++c) acc[a][b][c] = 0.0f;

    int nch = Kdim >> 6;

    auto stage_fill = [&](int ch, int stg) {
        int k0 = ch << 6;
        uint32_t sb = base_u + stg * STG;
#pragma unroll
        for (int t = 0; t < TOT / 256; ++t) {
            int i = tid + t * 256;
            // A: segs [0,1024), Whi: [1024,1536), Wlo: [1536,2048)
            int tensor = (i < 1024) ? 0 : ((i < 1536) ? 1 : 2);
            int s = i - ((tensor == 0) ? 0 : (tensor == 1) ? 1024 : 1536);
            uint32_t bo = (tensor == 0) ? 0u : ((tensor == 1) ? 16384u : 24576u);
            const __half* g = (tensor == 0) ? Ah : ((tensor == 1) ? Whi : Wlo);
            int r = s >> 3, cs = s & 7;
            int rr = ((tensor == 0) ? m0 : n0) + r;
            g += (size_t)rr * Kdim + k0 + cs * 8;
            uint32_t off = (uint32_t)(r * 128 + cs * 16);
            uint32_t sw = off ^ ((off >> 3) & 0x70);
            cp_async16(sb + bo + sw, g);
        }
        cp_commit();
    };

    if (TT) {
        stage_fill(0, 0);
    } else {
        stage_fill(0, 0);
        stage_fill(1, 1);
    }

    // hoisted ldsm address components (XOR mask depends only on lane&7)
    uint32_t xm = (uint32_t)(lane & 7) << 4;
    uint32_t a_base = (uint32_t)((wm + (lane & 15)) * 128 + ((lane >> 4) << 4));
    uint32_t w_base = (uint32_t)((wn + ((lane >> 3) & 1) * 8 + (lane & 7)) * 128
                                 + ((lane >> 4) << 4));

    for (int ch = 0; ch < nch; ++ch) {
        if (TT) {
            cp_wait<0>();
        } else {
            if (ch <= nch - 2) cp_wait<1>(); else cp_wait<0>();
        }
        __syncthreads();
        if (TT) {
            if (ch + 1 < nch) stage_fill(ch + 1, (ch + 1) & 1);
        } else {
            if (ch + 2 < nch) stage_fill(ch + 2, (ch + 2) % 3);
        }

        uint32_t sb = base_u + (ch % NSTG) * STG;
#pragma unroll
        for (int s = 0; s < 4; ++s) {
            uint32_t af[2][4];
#pragma unroll
            for (int mt = 0; mt < 2; ++mt)
                ldsm_x4(af[mt][0], af[mt][1], af[mt][2], af[mt][3],
                        sb + ((a_base + mt * 2048 + s * 32) ^ xm));
#pragma unroll
            for (int g16 = 0; g16 < 2; ++g16) {
                uint32_t wadr = (w_base + g16 * 2048 + s * 32) ^ xm;
                uint32_t h[4];
                ldsm_x4(h[0], h[1], h[2], h[3], sb + 16384 + wadr);
                if (TT) {
                    uint32_t l[4];
                    ldsm_x4(l[0], l[1], l[2], l[3], sb + 24576 + wadr);
#pragma unroll
                    for (int mt = 0; mt < 2; ++mt) {
                        mma_f16(acc[mt][2 * g16],     af[mt], h[0], h[2]);
                        mma_f16(acc[mt][2 * g16 + 1], af[mt], h[1], h[3]);
                    }
#pragma unroll
                    for (int mt = 0; mt < 2; ++mt) {
                        mma_f16(acc[mt][2 * g16],     af[mt], l[0], l[2]);
                        mma_f16(acc[mt][2 * g16 + 1], af[mt], l[1], l[3]);
                    }
                } else {
#pragma unroll
                    for (int mt = 0; mt < 2; ++mt) {
                        mma_f16(acc[mt][2 * g16],     af[mt], h[0], h[2]);
                        mma_f16(acc[mt][2 * g16 + 1], af[mt], h[1], h[3]);
                    }
                }
            }
        }
    }

    int r4 = lane >> 2, c2 = (lane & 3) * 2;
#pragma unroll
    for (int mt = 0; mt < 2; ++mt) {
        int row0 = m0 + wm + mt * 16 + r4;
#pragma unroll
        for (int nb = 0; nb < 4; ++nb) {
            int col = n0 + wn + nb * 8 + c2;
            float bx = bias[col], by = bias[col + 1];
            float2 v0 = {acc[mt][nb][0] + bx, acc[mt][nb][1] + by};
            float2 v1 = {acc[mt][nb][2] + bx, acc[mt][nb][3] + by};
            if (relu) {
                v0.x = fmaxf(v0.x, 0.f); v0.y = fmaxf(v0.y, 0.f);
                v1.x = fmaxf(v1.x, 0.f); v1.y = fmaxf(v1.y, 0.f);
            }
            size_t i0 = (size_t)row0 * Ndim + col;
            size_t i1 = (size_t)(row0 + 8) * Ndim + col;
            if (writeC) {
                *(float2*)&C[i0] = v0;
                *(float2*)&C[i1] = v1;
            }
            if (Ch) {
                *(__half2*)&Ch[i0] = __half2(__float2half(v0.x), __float2half(v0.y));
                *(__half2*)&Ch[i1] = __half2(__float2half(v1.x), __float2half(v1.y));
            }
        }
    }
}

// ---------------- fused attention per (b,h), 256 threads, f32x2, register scores ----------------
#define KROW 68
#define CBROW 36
#define ATTN_SMEM ((128 * KROW * 2 + 128 * CBROW) * 4)
__global__ __launch_bounds__(256, 2) void attn_kernel() {
    extern __shared__ float sm[];
    float* ks = sm;
    float* vs = sm + 128 * KROW;
    float* cb = sm + 2 * 128 * KROW;

    int bh = blockIdx.x;
    int b = bh >> 3, h = bh & 7;
    int tid = threadIdx.x;
    int row = tid & 127, jh = tid >> 7;
    const float* qkvb = g_qkv + (size_t)b * D_ * 3 * DM_;

    const float* krow = qkvb + (size_t)row * 3 * DM_ + DM_ + h * DH_ + jh * 32;
    const float* vrow = qkvb + (size_t)row * 3 * DM_ + 2 * DM_ + h * DH_ + jh * 32;
#pragma unroll
    for (int c = 0; c < 32; c += 4) {
        *(float4*)&ks[row * KROW + jh * 32 + c] = *(const float4*)(krow + c);
        *(float4*)&vs[row * KROW + jh * 32 + c] = *(const float4*)(vrow + c);
    }
    __syncthreads();

    float s[64];
    const float* qrow = qkvb + (size_t)row * 3 * DM_ + h * DH_;
#pragma unroll
    for (int ch2 = 0; ch2 < 2; ++ch2) {
        u64t q2[16];
        const u64t* q64 = (const u64t*)(qrow + ch2 * 32);
#pragma unroll
        for (int c = 0; c < 16; ++c) q2[c] = q64[c];
#pragma unroll 4
        for (int j0 = 0; j0 < 64; ++j0) {
            int jg = jh * 64 + j0;
            const u64t* k64 = (const u64t*)&ks[jg * KROW + ch2 * 32];
            u64t a2 = pk2(0.f, 0.f);
#pragma unroll
            for (int c = 0; c < 16; ++c) a2 = fma2(q2[c], k64[c], a2);
            float ax, ay; upk2(a2, ax, ay);
            s[j0] = (ch2 ? s[j0] : 0.0f) + ax + ay;
        }
    }
    float mx = -1e30f;
#pragma unroll
    for (int j = 0; j < 64; ++j) { s[j] *= 0.125f; mx = fmaxf(mx, s[j]); }
    cb[jh * 128 + row] = mx;
    __syncthreads();
    mx = fmaxf(cb[row], cb[128 + row]);
    float lsum = 0.0f;
#pragma unroll
    for (int j = 0; j < 64; ++j) { s[j] = __expf(s[j] - mx); lsum += s[j]; }
    cb[256 + jh * 128 + row] = lsum;
    __syncthreads();
    float inv = 1.0f / (cb[256 + row] + cb[384 + row]);
#pragma unroll
    for (int j = 0; j < 64; ++j) s[j] *= inv;

#pragma unroll
    for (int cp = 0; cp < 2; ++cp) {
        u64t a2[16];
#pragma unroll
        for (int c = 0; c < 16; ++c) a2[c] = pk2(0.f, 0.f);
#pragma unroll 4
        for (int j0 = 0; j0 < 64; ++j0) {
            int jg = jh * 64 + j0;
            u64t p2 = pk2(s[j0], s[j0]);
            const u64t* v64 = (const u64t*)&vs[jg * KROW + cp * 32];
#pragma unroll
            for (int c = 0; c < 16; ++c) a2[c] = fma2(p2, v64[c], a2[c]);
        }
        __syncthreads();
        if (jh == 0) {
#pragma unroll
            for (int c = 0; c < 16; ++c) {
                float ax, ay; upk2(a2[c], ax, ay);
                cb[row * CBROW + 2 * c] = ax;
                cb[row * CBROW + 2 * c + 1] = ay;
            }
        }
        __syncthreads();
        if (jh == 1) {
            size_t obase = ((size_t)b * D_ + row) * DM_ + h * DH_ + cp * 32;
#pragma unroll
            for (int c = 0; c < 16; ++c) {
                float ax, ay; upk2(a2[c], ax, ay);
                float fx = ax + cb[row * CBROW + 2 * c];
                float fy = ay + cb[row * CBROW + 2 * c + 1];
                *(__half2*)&g_ctxh[obase + 2 * c] = __floats2half2_rn(fx, fy);
            }
        }
    }
}

// ---------------- residual + layernorm, float4 vectorized ----------------
__global__ __launch_bounds__(128) void resid_ln_kernel(const float* __restrict__ y,
                                                       const float* __restrict__ gam,
                                                       const float* __restrict__ bet,
                                                       int has_res) {
    int row = blockIdx.x, tid = threadIdx.x;
    float* trow = g_t + (size_t)row * DM_;
    float4 tv = *(float4*)&trow[tid * 4];
    if (has_res) {
        float4 yv = *(const float4*)&y[(size_t)row * DM_ + tid * 4];
        tv.x += yv.x; tv.y += yv.y; tv.z += yv.z; tv.w += yv.w;
    }
    float s = tv.x + tv.y + tv.z + tv.w;
    float sq = tv.x * tv.x + tv.y * tv.y + tv.z * tv.z + tv.w * tv.w;
    __shared__ float rs[4], rq[4];
    unsigned lane = tid & 31, wid = tid >> 5;
#pragma unroll
    for (int off = 16; off; off >>= 1) {
        s += __shfl_down_sync(0xffffffffu, s, off);
        sq += __shfl_down_sync(0xffffffffu, sq, off);
    }
    if (lane == 0) { rs[wid] = s; rq[wid] = sq; }
    __syncthreads();
    float S = rs[0] + rs[1] + rs[2] + rs[3];
    float SQ = rq[0] + rq[1] + rq[2] + rq[3];
    float mean = S * (1.0f / (float)DM_);
    float var = SQ * (1.0f / (float)DM_) - mean * mean;
    float rstd = rsqrtf(var + 1e-5f);
    float4 g4 = *(const float4*)&gam[tid * 4];
    float4 b4 = *(const float4*)&bet[tid * 4];
    float4 o;
    o.x = (tv.x - mean) * rstd * g4.x + b4.x;
    o.y = (tv.y - mean) * rstd * g4.y + b4.y;
    o.z = (tv.z - mean) * rstd * g4.z + b4.z;
    o.w = (tv.w - mean) * rstd * g4.w + b4.w;
    *(float4*)&trow[tid * 4] = o;
    __half2* thp = (__half2*)&g_th[(size_t)row * DM_ + tid * 4];
    thp[0] = __floats2half2_rn(o.x, o.y);
    thp[1] = __floats2half2_rn(o.z, o.w);
}

// ---------------- head ----------------
__global__ __launch_bounds__(128) void head_kernel(const float* __restrict__ u,
                                                   const float* __restrict__ head_bias,
                                                   const float* __restrict__ lam,
                                                   float* __restrict__ out_y) {
    __shared__ float hps[M_];
    __shared__ float red[4];
    __shared__ float ybc;
    int blk = blockIdx.x;
    int b = blk >> 7, i = blk & 127;
    int tid = threadIdx.x;
    hps[tid] = g_hp[(size_t)blk * M_ + tid];
    __syncthreads();
    const float* lamb = lam + (size_t)b * D_ * D_;
    float acc = 0.0f;
    for (int k = 0; k < D_; ++k) acc += hps[k] * lamb[(size_t)k * D_ + tid];
    float p = acc * u[(size_t)i * M_ + tid];
    unsigned lane = tid & 31, wid = tid >> 5;
#pragma unroll
    for (int off = 16; off; off >>= 1) p += __shfl_down_sync(0xffffffffu, p, off);
    if (lane == 0) red[wid] = p;
    __syncthreads();
    if (tid == 0) ybc = red[0] + red[1] + red[2] + red[3] + head_bias[i];
    __syncthreads();
    float yv = ybc;
    if (tid < PRED_) out_y[(size_t)blk * PRED_ + tid] = yv;
}

// ---------------- host launcher ----------------
extern "C" void kernel_launch(void* const* d_in, const int* in_sizes, int n_in,
                              void* d_out, int out_size) {
    const float* x      = (const float*)d_in[0];
    const float* emb_w  = (const float*)d_in[1];
    const float* emb_b  = (const float*)d_in[2];
    const float* qkv_w  = (const float*)d_in[3];
    const float* qkv_b  = (const float*)d_in[4];
    const float* out_w  = (const float*)d_in[5];
    const float* out_b  = (const float*)d_in[6];
    const float* ln1_g  = (const float*)d_in[7];
    const float* ln1_b  = (const float*)d_in[8];
    const float* ln2_g  = (const float*)d_in[9];
    const float* ln2_b  = (const float*)d_in[10];
    const float* ff1_w  = (const float*)d_in[11];
    const float* ff1_b  = (const float*)d_in[12];
    const float* ff2_w  = (const float*)d_in[13];
    const float* ff2_b  = (const float*)d_in[14];
    const float* fn_g   = (const float*)d_in[15];
    const float* fn_b   = (const float*)d_in[16];
    const float* mlp1_w = (const float*)d_in[17];
    const float* mlp1_b = (const float*)d_in[18];
    const float* mlp2_w = (const float*)d_in[19];
    const float* mlp2_b = (const float*)d_in[20];
    const float* mlp3_w = (const float*)d_in[21];
    const float* mlp3_b = (const float*)d_in[22];
    const float* proj_w = (const float*)d_in[23];
    const float* proj_b = (const float*)d_in[24];
    const float* u      = (const float*)d_in[25];
    const float* hbias  = (const float*)d_in[26];

    float* out = (float*)d_out;
    float* out_lam = out + (size_t)B_ * D_ * PRED_;
    float* out_u = out_lam + (size_t)B_ * D_ * D_;

    float *t, *qkv, *y, *hp;
    __half *zh, *th, *ch, *mh, *whi, *wlo;
    cudaGetSymbolAddress((void**)&t, g_t);
    cudaGetSymbolAddress((void**)&qkv, g_qkv);
    cudaGetSymbolAddress((void**)&y, g_y);
    cudaGetSymbolAddress((void**)&hp, g_hp);
    cudaGetSymbolAddress((void**)&zh, g_zh);
    cudaGetSymbolAddress((void**)&th, g_th);
    cudaGetSymbolAddress((void**)&ch, g_ctxh);
    cudaGetSymbolAddress((void**)&mh, g_midh);
    cudaGetSymbolAddress((void**)&whi, g_whi);
    cudaGetSymbolAddress((void**)&wlo, g_wlo);

    cudaFuncSetAttribute(lam_kernel, cudaFuncAttributeMaxDynamicSharedMemorySize, 128 * 129 * 4);
    cudaFuncSetAttribute(attn_kernel, cudaFuncAttributeMaxDynamicSharedMemorySize, ATTN_SMEM);
    cudaFuncSetAttribute((void*)gemm_mma_kernel<1>,
                         cudaFuncAttributeMaxDynamicSharedMemorySize, GDYN);
    cudaFuncSetAttribute((void*)gemm_mma_kernel<0>,
                         cudaFuncAttributeMaxDynamicSharedMemorySize, GDYN);

    const int ROWS = B_ * D_;   // 8192

    // launches 1-3: prerequisites of the emb GEMM
    cvt_all_kernel<<<(2244608 + 255) / 256, 256>>>(emb_w, qkv_w, out_w, ff1_w, ff2_w, proj_w);
    transpose_x_kernel<<<dim3(L_ / 32, D_ / 32, B_), dim3(32, 8)>>>(x);
    copula_kernel<<<B_ * D_, 1024>>>();

    // launch 4: emb GEMM (profiled by ncu's bounded capture)
    gemm_mma_kernel<1><<<dim3(DM_ / 64, ROWS / 128), 256, GDYN>>>(
        zh, whi + OFF_EMB, wlo + OFF_EMB, emb_b, t, th, DM_, L_, 0, 1);

    // factor chain
    mlp12_kernel<<<B_, 64>>>(mlp1_w, mlp1_b, mlp2_w, mlp2_b);
    lower_kernel<<<dim3(B_, (D_ * M_) / 256), 256>>>(mlp3_w, mlp3_b);
    lam_kernel<<<B_, 256, 128 * 129 * 4>>>(out_lam);

    for (int l = 0; l < NL_; ++l) {
        gemm_mma_kernel<1><<<dim3(3 * DM_ / 64, ROWS / 128), 256, GDYN>>>(
            th, whi + OFF_QKV + (size_t)l * 3 * DM_ * DM_,
            wlo + OFF_QKV + (size_t)l * 3 * DM_ * DM_, qkv_b + (size_t)l * 3 * DM_,
            qkv, nullptr, 3 * DM_, DM_, 0, 1);
        attn_kernel<<<B_ * H_, 256, ATTN_SMEM>>>();
        gemm_mma_kernel<1><<<dim3(DM_ / 64, ROWS / 128), 256, GDYN>>>(
            ch, whi + OFF_OUT + (size_t)l * DM_ * DM_,
            wlo + OFF_OUT + (size_t)l * DM_ * DM_, out_b + (size_t)l * DM_,
            y, nullptr, DM_, DM_, 0, 1);
        resid_ln_kernel<<<ROWS, 128>>>(y, ln1_g + l * DM_, ln1_b + l * DM_, 1);
        gemm_mma_kernel<0><<<dim3(2 * DM_ / 64, ROWS / 128), 256, GDYN>>>(
            th, whi + OFF_FF1 + (size_t)l * 2 * DM_ * DM_,
            wlo + OFF_FF1 + (size_t)l * 2 * DM_ * DM_, ff1_b + (size_t)l * 2 * DM_,
            nullptr, mh, 2 * DM_, DM_, 1, 0);
        gemm_mma_kernel<0><<<dim3(DM_ / 64, ROWS / 128), 256, GDYN>>>(
            mh, whi + OFF_FF2 + (size_t)l * DM_ * 2 * DM_,
            wlo + OFF_FF2 + (size_t)l * DM_ * 2 * DM_, ff2_b + (size_t)l * DM_,
            y, nullptr, DM_, 2 * DM_, 0, 1);
        resid_ln_kernel<<<ROWS, 128>>>(y, ln2_g + l * DM_, ln2_b + l * DM_, 1);
    }

    resid_ln_kernel<<<ROWS, 128>>>(y, fn_g, fn_b, 0);

    gemm_mma_kernel<1><<<dim3(M_ / 64, ROWS / 128), 256, GDYN>>>(
        th, whi + OFF_PROJ, wlo + OFF_PROJ, proj_b, hp, nullptr, M_, DM_, 0, 1);
    head_kernel<<<ROWS, 128>>>(u, hbias, out_lam, out);

    cudaMemcpyAsync(out_u, u, (size_t)D_ * M_ * sizeof(float), cudaMemcpyDeviceToDevice);
}